// round 17
// baseline (speedup 1.0000x reference)
#include <cuda_runtime.h>
#include <cstdint>

#define N_Q   2048
#define N_P   256
#define EMB   512
#define NM    5
#define HID   64
#define KSPL  2
#define KHALF (EMB / KSPL)    // 256 K per gemm block

// Scratch (allocation-free rule: __device__ globals)
__device__ float g_hq[KSPL][NM * N_Q * HID];     // partials
__device__ float g_hp[KSPL][NM * N_P * HID];
__device__ float g_rsq_p[KSPL][NM * N_Q];        // rowsum partials
__device__ float g_rsp_p[KSPL][NM * N_P];
__device__ float g_hqs[NM * N_Q * HID];          // summed
__device__ float g_hps[NM * N_P * HID];
__device__ float g_rsq[NM * N_Q];
__device__ float g_rsp[NM * N_P];

// ===========================================================================
// Kernel 1: bf16 HMMA GEMM, 3-term hi/lo split, K-SPLIT 2 + double buffer.
// Block 64 rows x 64 h, 128 threads, K=256 per block in 4 chunks of 64.
// grid (36, 5, 2) = 360 blocks -> makespan 3 half-blocks (was 2 full).
// Epilogue: partial tile store + partial rowsum (dot with w2/2).
// ===========================================================================
#define SM_AHI 0
#define SM_ALO 16384
#define SM_WHI 32768
#define SM_WLO 40960
#define BUFB   49152
#define GEMM_SMEM (2 * BUFB)

__device__ __forceinline__ uint32_t smem_u32(const void* p) {
    uint32_t a;
    asm("{ .reg .u64 t; cvta.to.shared.u64 t, %1; cvt.u32.u64 %0, t; }"
        : "=r"(a) : "l"(p));
    return a;
}

#define LDSM4(r, addr)                                                       \
    asm volatile("ldmatrix.sync.aligned.m8n8.x4.shared.b16 "                 \
                 "{%0,%1,%2,%3}, [%4];"                                      \
                 : "=r"((r)[0]), "=r"((r)[1]), "=r"((r)[2]), "=r"((r)[3])    \
                 : "r"(addr))

#define MMA16816(d, a, b0v, b1v)                                             \
    asm volatile("mma.sync.aligned.m16n8k16.row.col.f32.bf16.bf16.f32 "      \
                 "{%0,%1,%2,%3}, {%4,%5,%6,%7}, {%8,%9}, {%0,%1,%2,%3};"     \
                 : "+f"((d)[0]), "+f"((d)[1]), "+f"((d)[2]), "+f"((d)[3])    \
                 : "r"((a)[0]), "r"((a)[1]), "r"((a)[2]), "r"((a)[3]),       \
                   "r"(b0v), "r"(b1v))

__device__ __forceinline__ void split8(float4 a, float4 b, uint4& hi, uint4& lo) {
    asm("cvt.rn.bf16x2.f32 %0, %1, %2;" : "=r"(hi.x) : "f"(a.y), "f"(a.x));
    asm("cvt.rn.bf16x2.f32 %0, %1, %2;" : "=r"(hi.y) : "f"(a.w), "f"(a.z));
    asm("cvt.rn.bf16x2.f32 %0, %1, %2;" : "=r"(hi.z) : "f"(b.y), "f"(b.x));
    asm("cvt.rn.bf16x2.f32 %0, %1, %2;" : "=r"(hi.w) : "f"(b.w), "f"(b.z));
    float h0 = __uint_as_float(hi.x << 16), h1 = __uint_as_float(hi.x & 0xFFFF0000u);
    float h2 = __uint_as_float(hi.y << 16), h3 = __uint_as_float(hi.y & 0xFFFF0000u);
    float h4 = __uint_as_float(hi.z << 16), h5 = __uint_as_float(hi.z & 0xFFFF0000u);
    float h6 = __uint_as_float(hi.w << 16), h7 = __uint_as_float(hi.w & 0xFFFF0000u);
    asm("cvt.rn.bf16x2.f32 %0, %1, %2;" : "=r"(lo.x) : "f"(a.y - h1), "f"(a.x - h0));
    asm("cvt.rn.bf16x2.f32 %0, %1, %2;" : "=r"(lo.y) : "f"(a.w - h3), "f"(a.z - h2));
    asm("cvt.rn.bf16x2.f32 %0, %1, %2;" : "=r"(lo.z) : "f"(b.y - h5), "f"(b.x - h4));
    asm("cvt.rn.bf16x2.f32 %0, %1, %2;" : "=r"(lo.w) : "f"(b.w - h7), "f"(b.z - h6));
}

__global__ __launch_bounds__(128) void gemm_mma_kernel(
    const float* __restrict__ Q, const float* __restrict__ P,
    const float* __restrict__ W1, const float* __restrict__ b1,
    const float* __restrict__ W2)
{
    extern __shared__ __align__(128) char smem[];
    const uint32_t sb = smem_u32(smem);

    const int tid  = threadIdx.x;
    const int wid  = tid >> 5;
    const int lane = tid & 31;

    const int m  = blockIdx.y;
    const int kh = blockIdx.z;
    const int rt = blockIdx.x;
    const bool is_q = rt < (N_Q / 64);

    const float* src;
    int row0;
    float* dst;
    float* rs_dst;
    if (is_q) {
        src = Q;  row0 = rt * 64;
        dst = &g_hq[kh][(size_t)(m * N_Q + row0) * HID];
        rs_dst = &g_rsq_p[kh][m * N_Q + row0];
    } else {
        src = P;  row0 = (rt - N_Q / 64) * 64;
        dst = &g_hp[kh][(size_t)(m * N_P + row0) * HID];
        rs_dst = &g_rsp_p[kh][m * N_P + row0];
    }
    const float* Sb = src + (size_t)row0 * EMB + kh * KHALF;
    const float* Wb = W1 + (size_t)m * HID * (2 * EMB) + (is_q ? 0 : EMB) + kh * KHALF;

    const int st_row = tid >> 3;
    const int st_kg  = tid & 7;

    float4 pa[8], pw[8];
    auto ldg_chunk = [&](int c) {
        const int kt = c * 64;
        #pragma unroll
        for (int i = 0; i < 4; i++) {
            int row = st_row + i * 16;
            const float* g  = Sb + (size_t)row * EMB + kt + st_kg * 8;
            const float* gw = Wb + (size_t)row * (2 * EMB) + kt + st_kg * 8;
            pa[2 * i]     = *(const float4*)g;
            pa[2 * i + 1] = *(const float4*)(g + 4);
            pw[2 * i]     = *(const float4*)gw;
            pw[2 * i + 1] = *(const float4*)(gw + 4);
        }
    };
    auto sts_chunk = [&](int b) {
        char* base = smem + b * BUFB;
        #pragma unroll
        for (int i = 0; i < 4; i++) {
            int row = st_row + i * 16;
            uint32_t off = (uint32_t)(row * 128 + ((st_kg ^ (row & 7)) << 4));
            uint4 hi, lo;
            split8(pa[2 * i], pa[2 * i + 1], hi, lo);
            *(uint4*)(base + SM_AHI + off) = hi;
            *(uint4*)(base + SM_ALO + off) = lo;
            split8(pw[2 * i], pw[2 * i + 1], hi, lo);
            *(uint4*)(base + SM_WHI + off) = hi;
            *(uint4*)(base + SM_WLO + off) = lo;
        }
    };

    const int rA    = wid * 16 + (lane & 15);
    const int rx7A  = rA & 7;
    const int kselA = lane >> 4;
    const int rB_loc  = ((lane >> 4) & 1) * 8 + (lane & 7);
    const int kgB_add = (lane >> 3) & 1;

    float acc[8][4] = {};

    ldg_chunk(0);
    sts_chunk(0);
    __syncthreads();

    for (int c = 0; c < 4; c++) {
        const uint32_t bufo = sb + (uint32_t)(c & 1) * BUFB;
        if (c < 3) ldg_chunk(c + 1);

        #pragma unroll
        for (int ks = 0; ks < 4; ks++) {
            const int kgA = ks * 2 + kselA;
            const uint32_t aoff = (uint32_t)(rA * 128 + ((kgA ^ rx7A) << 4));
            uint32_t ahi[4], alo[4];
            LDSM4(ahi, bufo + SM_AHI + aoff);
            LDSM4(alo, bufo + SM_ALO + aoff);

            #pragma unroll
            for (int j = 0; j < 4; j++) {
                const int rB  = j * 16 + rB_loc;
                const int kgB = ks * 2 + kgB_add;
                const uint32_t boff = (uint32_t)(rB * 128 + ((kgB ^ (rB & 7)) << 4));
                uint32_t bhi[4], blo[4];
                LDSM4(bhi, bufo + SM_WHI + boff);
                LDSM4(blo, bufo + SM_WLO + boff);

                MMA16816(acc[2 * j],     ahi, bhi[0], bhi[1]);
                MMA16816(acc[2 * j],     ahi, blo[0], blo[1]);
                MMA16816(acc[2 * j],     alo, bhi[0], bhi[1]);
                MMA16816(acc[2 * j + 1], ahi, bhi[2], bhi[3]);
                MMA16816(acc[2 * j + 1], ahi, blo[2], blo[3]);
                MMA16816(acc[2 * j + 1], alo, bhi[2], bhi[3]);
            }
        }

        if (c < 3) sts_chunk((c + 1) & 1);
        __syncthreads();
    }

    // Epilogue: store partial (+b1 only on kh==0 for q), partial rowsum.
    const int er = lane >> 2;
    const int ec = (lane & 3) * 2;
    float* d0 = dst + (size_t)(wid * 16 + er) * HID;
    float* d1 = dst + (size_t)(wid * 16 + er + 8) * HID;
    const bool add_b1 = is_q && (kh == 0);

    float wp[16];
    #pragma unroll
    for (int nf = 0; nf < 8; nf++) {
        float2 wv = *(const float2*)(W2 + m * HID + nf * 8 + ec);
        wp[2 * nf]     = 0.5f * wv.x;
        wp[2 * nf + 1] = 0.5f * wv.y;
    }

    float r0 = 0.f, r1 = 0.f;
    #pragma unroll
    for (int nf = 0; nf < 8; nf++) {
        float bx = 0.f, by = 0.f;
        if (add_b1) {
            float2 bv = *(const float2*)(b1 + m * HID + nf * 8 + ec);
            bx = bv.x; by = bv.y;
        }
        float o00 = acc[nf][0] + bx, o01 = acc[nf][1] + by;
        float o10 = acc[nf][2] + bx, o11 = acc[nf][3] + by;
        *(float2*)(d0 + nf * 8 + ec) = make_float2(o00, o01);
        *(float2*)(d1 + nf * 8 + ec) = make_float2(o10, o11);
        r0 += o00 * wp[2 * nf] + o01 * wp[2 * nf + 1];
        r1 += o10 * wp[2 * nf] + o11 * wp[2 * nf + 1];
    }
    r0 += __shfl_xor_sync(0xFFFFFFFF, r0, 1);
    r0 += __shfl_xor_sync(0xFFFFFFFF, r0, 2);
    r1 += __shfl_xor_sync(0xFFFFFFFF, r1, 1);
    r1 += __shfl_xor_sync(0xFFFFFFFF, r1, 2);
    if ((lane & 3) == 0) {
        rs_dst[wid * 16 + er]     = r0;
        rs_dst[wid * 16 + er + 8] = r1;
    }
}

// ===========================================================================
// Kernel 2: sum the 2 K-split partials (tiles + rowsums). L2-resident.
// ===========================================================================
#define HQ4  (NM * N_Q * HID / 4)     // 163840
#define HP4  (NM * N_P * HID / 4)     // 20480
#define RSQ4 (NM * N_Q / 4)           // 2560
#define RSP4 (NM * N_P / 4)           // 320
#define SUM_TOTAL (HQ4 + HP4 + RSQ4 + RSP4)

__device__ __forceinline__ float4 f4add(float4 a, float4 b) {
    return make_float4(a.x + b.x, a.y + b.y, a.z + b.z, a.w + b.w);
}

__global__ __launch_bounds__(256) void sum_partials_kernel()
{
    int i = blockIdx.x * 256 + threadIdx.x;
    if (i >= SUM_TOTAL) return;
    if (i < HQ4) {
        ((float4*)g_hqs)[i] = f4add(((const float4*)g_hq[0])[i],
                                    ((const float4*)g_hq[1])[i]);
    } else if (i < HQ4 + HP4) {
        int j = i - HQ4;
        ((float4*)g_hps)[j] = f4add(((const float4*)g_hp[0])[j],
                                    ((const float4*)g_hp[1])[j]);
    } else if (i < HQ4 + HP4 + RSQ4) {
        int j = i - HQ4 - HP4;
        ((float4*)g_rsq)[j] = f4add(((const float4*)g_rsq_p[0])[j],
                                    ((const float4*)g_rsq_p[1])[j]);
    } else {
        int j = i - HQ4 - HP4 - RSQ4;
        ((float4*)g_rsp)[j] = f4add(((const float4*)g_rsp_p[0])[j],
                                    ((const float4*)g_rsp_p[1])[j]);
    }
}

// ===========================================================================
// Kernel 3: fused |.|-combine + ensemble stats (R13 shape, measured best)
// with EXPLICIT REGISTER DOUBLE-BUFFERING of X/Y/W fragments to hide the
// 29-cyc LDS latency (the identified issue-efficiency limiter).
// Tile: 64q x 32p, 128 threads, 4x4 outputs/thread. grid (32,8)=256 blocks.
// ===========================================================================
#define BQ 64
#define BP 32
#define BUF_FLOATS ((BQ + BP) * HID)              // 6144 floats = 24 KB
#define RS_PER_M   (BQ + BP)                      // 96
#define SMEM_FLOATS (2 * BUF_FLOATS + NM * HID + NM * RS_PER_M + 8)
#define SMEM_BYTES  (SMEM_FLOATS * 4)

#define ABS_FMA2(acc, x2, y2, w2)                                     \
    asm("{\n\t"                                                       \
        ".reg .b64 s;\n\t"                                            \
        "add.rn.f32x2 s, %1, %2;\n\t"                                 \
        "and.b64 s, s, 0x7FFFFFFF7FFFFFFF;\n\t"                       \
        "fma.rn.f32x2 %0, s, %3, %0;\n\t"                             \
        "}"                                                           \
        : "+l"(acc) : "l"(x2), "l"(y2), "l"(w2))

__device__ __forceinline__ void cpa16(void* smem_ptr, const void* gptr) {
    uint32_t s = (uint32_t)__cvta_generic_to_shared(smem_ptr);
    asm volatile("cp.async.cg.shared.global [%0], [%1], 16;" :: "r"(s), "l"(gptr));
}

__global__ __launch_bounds__(128) void final_kernel(
    const float* __restrict__ W2, const float* __restrict__ b2,
    float* __restrict__ out)
{
    extern __shared__ float smem_f[];
    float* s_w2 = smem_f + 2 * BUF_FLOATS;     // [NM][HID], prescaled 0.5
    float* s_rs = s_w2 + NM * HID;             // [NM][96]: 64 q then 32 p
    float* s_b2 = s_rs + NM * RS_PER_M;

    const int tid = threadIdx.x;               // 0..127
    const int q0  = blockIdx.x * BQ;
    const int p0  = blockIdx.y * BP;
    const int tyq = tid >> 3;                  // 0..15 -> q rows tyq*4..+3
    const int txp = tid & 7;                   // 0..7  -> p rows txp*4..+3

    for (int i = tid; i < NM * HID; i += 128) s_w2[i] = 0.5f * W2[i];
    for (int i = tid; i < NM * RS_PER_M; i += 128) {
        int m = i / RS_PER_M;
        int r = i % RS_PER_M;
        s_rs[i] = (r < BQ) ? g_rsq[m * N_Q + q0 + r]
                           : g_rsp[m * N_P + p0 + (r - BQ)];
    }
    if (tid < NM) s_b2[tid] = b2[tid];

    // stage one model's tiles: x 64x16 f4 + y 32x16 f4 = 1536 -> 12/thread
    auto stage = [&](int m, int b) {
        float* base = smem_f + b * BUF_FLOATS;
        #pragma unroll
        for (int k = 0; k < 12; k++) {
            int idx = tid + k * 128;
            const float* g;
            float* s;
            if (idx < 1024) {
                int row = idx >> 4;
                int c4  = idx & 15;
                int sc  = ((c4 ^ (row >> 2)) & 15) * 4;
                g = g_hqs + ((size_t)(m * N_Q + q0 + row)) * HID + c4 * 4;
                s = base + row * HID + sc;
            } else {
                int t   = idx - 1024;
                int row = t >> 4;
                int c4  = t & 15;
                int sc  = ((c4 ^ (row >> 2)) & 15) * 4;
                g = g_hps + ((size_t)(m * N_P + p0 + row)) * HID + c4 * 4;
                s = base + (BQ + row) * HID + sc;
            }
            cpa16(s, g);
        }
        asm volatile("cp.async.commit_group;");
    };

    stage(0, 0);
    stage(1, 1);

    float sum[4][4] = {};
    float sq [4][4] = {};

    for (int m = 0; m < NM; m++) {
        if (m < NM - 1) {
            asm volatile("cp.async.wait_group 1;");
        } else {
            asm volatile("cp.async.wait_group 0;");
        }
        __syncthreads();

        const float* bx   = smem_f + (m & 1) * BUF_FLOATS;
        const float* xrow = bx + (tyq * 4) * HID;
        const float* yrow = bx + (BQ + txp * 4) * HID;
        const float* wrow = s_w2 + m * HID;

        unsigned long long acc[4][4] = {};

        // register double-buffer: load c4+1 fragments during c4's math
        ulonglong2 Xr[2][4], Yr[2][4], Wr[2];
        {
            int cx = (tyq & 15) * 4;       // c4 = 0
            int cy = (txp & 15) * 4;
            #pragma unroll
            for (int i = 0; i < 4; i++)
                Xr[0][i] = *(const ulonglong2*)(xrow + i * HID + cx);
            #pragma unroll
            for (int j = 0; j < 4; j++)
                Yr[0][j] = *(const ulonglong2*)(yrow + j * HID + cy);
            Wr[0] = *(const ulonglong2*)(wrow);
        }

        #pragma unroll 4
        for (int c4 = 0; c4 < 16; c4++) {
            const int cb = c4 & 1;
            const int nb = cb ^ 1;
            if (c4 < 15) {
                int cx = (((c4 + 1) ^ tyq) & 15) * 4;
                int cy = (((c4 + 1) ^ txp) & 15) * 4;
                #pragma unroll
                for (int i = 0; i < 4; i++)
                    Xr[nb][i] = *(const ulonglong2*)(xrow + i * HID + cx);
                #pragma unroll
                for (int j = 0; j < 4; j++)
                    Yr[nb][j] = *(const ulonglong2*)(yrow + j * HID + cy);
                Wr[nb] = *(const ulonglong2*)(wrow + (c4 + 1) * 4);
            }
            #pragma unroll
            for (int i = 0; i < 4; i++)
                #pragma unroll
                for (int j = 0; j < 4; j++) {
                    ABS_FMA2(acc[i][j], Xr[cb][i].x, Yr[cb][j].x, Wr[cb].x);
                    ABS_FMA2(acc[i][j], Xr[cb][i].y, Yr[cb][j].y, Wr[cb].y);
                }
        }

        float bb = s_b2[m];
        float rsx[4], rsy[4];
        #pragma unroll
        for (int i = 0; i < 4; i++) rsx[i] = s_rs[m * RS_PER_M + tyq * 4 + i] + bb;
        #pragma unroll
        for (int j = 0; j < 4; j++) rsy[j] = s_rs[m * RS_PER_M + BQ + txp * 4 + j];

        #pragma unroll
        for (int i = 0; i < 4; i++)
            #pragma unroll
            for (int j = 0; j < 4; j++) {
                unsigned long long a = acc[i][j];
                float lo = __uint_as_float((unsigned)(a & 0xFFFFFFFFull));
                float hi = __uint_as_float((unsigned)(a >> 32));
                float o  = lo + hi + rsx[i] + rsy[j];
                sum[i][j] += o;
                sq [i][j] += o * o;
            }

        __syncthreads();
        if (m + 2 < NM) stage(m + 2, m & 1);
    }

    #pragma unroll
    for (int i = 0; i < 4; i++) {
        float4 r4;
        float* rp = (float*)&r4;
        #pragma unroll
        for (int j = 0; j < 4; j++) {
            float mean = sum[i][j] * 0.2f;
            float var  = fmaxf(sq[i][j] - 5.0f * mean * mean, 0.0f) * 0.25f; // ddof=1
            rp[j] = mean * expf(-sqrtf(var));
        }
        int q = q0 + tyq * 4 + i;
        *(float4*)(out + (size_t)q * N_P + p0 + txp * 4) = r4;
    }
}

// ---------------------------------------------------------------------------
extern "C" void kernel_launch(void* const* d_in, const int* in_sizes, int n_in,
                              void* d_out, int out_size)
{
    const float* Q  = (const float*)d_in[0];
    const float* P  = (const float*)d_in[1];
    const float* W1 = (const float*)d_in[2];
    const float* b1 = (const float*)d_in[3];
    const float* W2 = (const float*)d_in[4];
    const float* b2 = (const float*)d_in[5];
    float* out = (float*)d_out;

    cudaFuncSetAttribute(gemm_mma_kernel,
                         cudaFuncAttributeMaxDynamicSharedMemorySize, GEMM_SMEM);
    dim3 g1(N_Q / 64 + N_P / 64, NM, KSPL);       // (36, 5, 2) = 360 blocks
    gemm_mma_kernel<<<g1, 128, GEMM_SMEM>>>(Q, P, W1, b1, W2);

    sum_partials_kernel<<<(SUM_TOTAL + 255) / 256, 256>>>();

    cudaFuncSetAttribute(final_kernel,
                         cudaFuncAttributeMaxDynamicSharedMemorySize, SMEM_BYTES);
    dim3 g3(N_Q / BQ, N_P / BP);                  // (32, 8) = 256 blocks
    final_kernel<<<g3, 128, SMEM_BYTES>>>(W2, b2, out);
}